// round 17
// baseline (speedup 1.0000x reference)
#include <cuda_runtime.h>

#define KTAGS 48
#define TLEN 1024
#define STOPID 47
#define NEGV (-10000.0f)

__device__ __forceinline__ unsigned long long pk2(float lo, float hi) {
    unsigned long long r;
    asm("mov.b64 %0, {%1, %2};" : "=l"(r) : "f"(lo), "f"(hi));
    return r;
}
__device__ __forceinline__ void upk2(unsigned long long v, float& lo, float& hi) {
    asm("mov.b64 {%0, %1}, %2;" : "=f"(lo), "=f"(hi) : "l"(v));
}
// d = a*b + d  (packed f32x2 -> SASS FFMA2)
__device__ __forceinline__ void fma2(unsigned long long& d, unsigned long long a, unsigned long long b) {
    asm("fma.rn.f32x2 %0, %1, %2, %0;" : "+l"(d) : "l"(a), "l"(b));
}
__device__ __forceinline__ void add2(unsigned long long& d, unsigned long long a) {
    asm("add.rn.f32x2 %0, %0, %1;" : "+l"(d) : "l"(a));
}

// Renorm: exact power-of-2 scale from the warp-max exponent. All v >= 0.
__device__ __forceinline__ void renorm3(float& v0, float& v1, float& vB, int& Mint) {
    float lmax = fmaxf(fmaxf(v0, v1), vB);
    unsigned mxb = __reduce_max_sync(0xffffffffu, __float_as_uint(lmax));
    int ebx = (int)(mxb >> 23);                              // biased exponent of max
    float r = __uint_as_float((unsigned)(254 - ebx) << 23);  // 2^(127-eb)
    v0 *= r; v1 *= r; vB *= r;
    Mint += ebx - 127;
}

// Two same-direction chains (batches X, Y) interleaved in one warp; they share
// the E registers. Row mapping (zero duplication): lane l owns rows r0=(l&15),
// r1=16+(l&15), rB=32+(l&15) over j-half [24*(l>=16),+24); 36 FFMA2/chain/step,
// halves merged by shfl_xor(16). Chain Y's fma window hides chain X's
// sync/LDS/shfl latency and vice versa.
// FWD: alpha' = D_t E alpha,  s=1..511 (t=s).
// !FWD: beta' = E^T D_t beta, s=1..512 (t=1024-s).
// Renorm every 8 steps (worst-case growth ~e^64 < fp32 max e^88) + final renorm.
template <bool FWD>
__device__ __forceinline__ void run_chain2(
    const float* __restrict__ ebX, const float* __restrict__ mbX,
    const float* __restrict__ ebY, const float* __restrict__ mbY,
    const unsigned long long* E0, const unsigned long long* E1,
    const unsigned long long* EBr,
    float& x0, float& x1, float& xB, int& MintX,
    float& y0, float& y1, float& yB, int& MintY,
    float* __restrict__ bufX0, float* __restrict__ bufX1,
    float* __restrict__ bufY0, float* __restrict__ bufY1,
    int lane)
{
    const int l16 = lane & 15;
    const bool lo = (lane < 16);
    const int r0 = l16, r1 = 16 + l16, rB = 32 + l16;
    const int jb = lo ? 0 : 24;                    // j-half base

    float nx0[4], nx1[4], nxB[4], nxM[4];
    float ny0[4], ny1[4], nyB[4], nyM[4];
    #pragma unroll
    for (int u = 0; u < 4; ++u) {
        int s = 1 + u;
        int t = FWD ? s : (TLEN - s);
        nx0[u] = ebX[t * KTAGS + r0]; nx1[u] = ebX[t * KTAGS + r1];
        nxB[u] = ebX[t * KTAGS + rB]; nxM[u] = mbX[t];
        ny0[u] = ebY[t * KTAGS + r0]; ny1[u] = ebY[t * KTAGS + r1];
        nyB[u] = ebY[t * KTAGS + rB]; nyM[u] = mbY[t];
    }

    float* xcur = bufX0; float* xnxt = bufX1;
    float* ycur = bufY0; float* ynxt = bufY1;

    for (int base = 1; base < 513; base += 4) {
        // hoist the group's exps off the per-step chains
        float ex0[4], ex1[4], exB[4], cxM[4];
        float ey0[4], ey1[4], eyB[4], cyM[4];
        #pragma unroll
        for (int u = 0; u < 4; ++u) {
            ex0[u] = __expf(nx0[u]); ex1[u] = __expf(nx1[u]);
            exB[u] = __expf(nxB[u]); cxM[u] = nxM[u];
            ey0[u] = __expf(ny0[u]); ey1[u] = __expf(ny1[u]);
            eyB[u] = __expf(nyB[u]); cyM[u] = nyM[u];
        }
        #pragma unroll
        for (int u = 0; u < 4; ++u) {
            int s = base + 4 + u;                  // max 516; t valid both directions
            int t = FWD ? s : (TLEN - s);
            nx0[u] = ebX[t * KTAGS + r0]; nx1[u] = ebX[t * KTAGS + r1];
            nxB[u] = ebX[t * KTAGS + rB]; nxM[u] = mbX[t];
            ny0[u] = ebY[t * KTAGS + r0]; ny1[u] = ebY[t * KTAGS + r1];
            nyB[u] = ebY[t * KTAGS + rB]; nyM[u] = mbY[t];
        }
        #pragma unroll
        for (int u = 0; u < 4; ++u) {
            int s = base + u;
            if (FWD && s > 511) break;             // fwd: 511 loop steps; bwd: 512

            // fwd stores v (emission applied after matvec); bwd stores v*exp(e)
            float wx0 = FWD ? x0 : x0 * ex0[u];
            float wx1 = FWD ? x1 : x1 * ex1[u];
            float wxB = FWD ? xB : xB * exB[u];
            float wy0 = FWD ? y0 : y0 * ey0[u];
            float wy1 = FWD ? y1 : y1 * ey1[u];
            float wyB = FWD ? yB : yB * eyB[u];
            if (lo) { xcur[r0] = wx0; xcur[r1] = wx1; ycur[r0] = wy0; ycur[r1] = wy1; }
            else    { xcur[rB] = wxB; ycur[rB] = wyB; }
            __syncwarp();

            // each lane loads only its j-half: 6 LDS.128 per chain
            const ulonglong2* vpx = (const ulonglong2*)(xcur + jb);
            const ulonglong2* vpy = (const ulonglong2*)(ycur + jb);
            ulonglong2 wx[6], wy[6];
            #pragma unroll
            for (int k = 0; k < 6; ++k) { wx[k] = vpx[k]; wy[k] = vpy[k]; }

            unsigned long long aX0[2] = {0,0}, aX1[2] = {0,0}, aXB[2] = {0,0};
            unsigned long long aY0[2] = {0,0}, aY1[2] = {0,0}, aYB[2] = {0,0};
            #pragma unroll
            for (int k = 0; k < 6; ++k) {
                fma2(aX0[0], E0[2 * k],      wx[k].x);
                fma2(aX0[1], E0[2 * k + 1],  wx[k].y);
                fma2(aY0[0], E0[2 * k],      wy[k].x);
                fma2(aY0[1], E0[2 * k + 1],  wy[k].y);
                fma2(aX1[0], E1[2 * k],      wx[k].x);
                fma2(aX1[1], E1[2 * k + 1],  wx[k].y);
                fma2(aY1[0], E1[2 * k],      wy[k].x);
                fma2(aY1[1], E1[2 * k + 1],  wy[k].y);
                fma2(aXB[0], EBr[2 * k],     wx[k].x);
                fma2(aXB[1], EBr[2 * k + 1], wx[k].y);
                fma2(aYB[0], EBr[2 * k],     wy[k].x);
                fma2(aYB[1], EBr[2 * k + 1], wy[k].y);
            }
            add2(aX0[0], aX0[1]); add2(aX1[0], aX1[1]); add2(aXB[0], aXB[1]);
            add2(aY0[0], aY0[1]); add2(aY1[0], aY1[1]); add2(aYB[0], aYB[1]);

            float l, h;
            upk2(aX0[0], l, h); float dX0h = l + h;
            upk2(aX1[0], l, h); float dX1h = l + h;
            upk2(aXB[0], l, h); float dXBh = l + h;
            upk2(aY0[0], l, h); float dY0h = l + h;
            upk2(aY1[0], l, h); float dY1h = l + h;
            upk2(aYB[0], l, h); float dYBh = l + h;
            // merge the two j-halves (symmetric: both halves get the full dot)
            float dX0 = dX0h + __shfl_xor_sync(0xffffffffu, dX0h, 16);
            float dX1 = dX1h + __shfl_xor_sync(0xffffffffu, dX1h, 16);
            float dXB = dXBh + __shfl_xor_sync(0xffffffffu, dXBh, 16);
            float dY0 = dY0h + __shfl_xor_sync(0xffffffffu, dY0h, 16);
            float dY1 = dY1h + __shfl_xor_sync(0xffffffffu, dY1h, 16);
            float dYB = dYBh + __shfl_xor_sync(0xffffffffu, dYBh, 16);

            bool liveX = (cxM[u] != 0.f);
            bool liveY = (cyM[u] != 0.f);
            x0 = liveX ? (FWD ? dX0 * ex0[u] : dX0) : x0;
            x1 = liveX ? (FWD ? dX1 * ex1[u] : dX1) : x1;
            xB = liveX ? (FWD ? dXB * exB[u] : dXB) : xB;
            y0 = liveY ? (FWD ? dY0 * ey0[u] : dY0) : y0;
            y1 = liveY ? (FWD ? dY1 * ey1[u] : dY1) : y1;
            yB = liveY ? (FWD ? dYB * eyB[u] : dYB) : yB;

            // renorm every 8 steps: groups base=5,13,... at u==3 -> s=8,16,...
            if ((u == 3) && ((base & 4) != 0)) {
                renorm3(x0, x1, xB, MintX);
                renorm3(y0, y1, yB, MintY);
            }
            float* tp;
            tp = xcur; xcur = xnxt; xnxt = tp;
            tp = ycur; ycur = ynxt; ynxt = tp;
        }
    }
    renorm3(x0, x1, xB, MintX);                    // bound v before alpha*beta combine
    renorm3(y0, y1, yB, MintY);
}

// One block = 4 batches, 4 warps (one per SMSP, 1 warp/SMSP chip-wide):
//   warp0 = fwd(b0,b1), warp1 = bwd(b0,b1), warp2 = fwd(b2,b3), warp3 = bwd(b2,b3).
// Z = Mf + Mb + log(sum_i alphaHat_i * betaHat_i).
__global__ __launch_bounds__(128, 1)
void CRF_29265907155259_kernel(const float* __restrict__ h_tag,
                               const float* __restrict__ mask,
                               const float* __restrict__ trans,
                               float* __restrict__ out, int B)
{
    __shared__ __align__(16) float vbuf[4][2][2][KTAGS];  // [warp][chain][pp][tag]
    __shared__ float cbuf[2][4][KTAGS];                   // [dir][batchInBlk][tag]
    __shared__ double Msh[2][4];

    const int lane = threadIdx.x & 31;
    const int warp = threadIdx.x >> 5;
    const bool fwd = ((warp & 1) == 0);
    const int pair = warp >> 1;                // 0 or 1
    const int bloc = pair * 2;                 // local batch base (0 or 2)
    int bg0 = blockIdx.x * 4 + bloc;
    int bX = (bg0 < B) ? bg0 : (B - 1);        // clamp; duplicate work keeps syncs safe
    int bY = (bg0 + 1 < B) ? (bg0 + 1) : (B - 1);

    const int l16 = lane & 15;
    const bool lo = (lane < 16);
    const int r0 = l16, r1 = 16 + l16, rB = 32 + l16;
    const int jb = lo ? 0 : 24;

    // ---- E = exp(trans) (fwd) or exp(trans)^T (bwd): per-lane j-half rows ----
    unsigned long long E0[12], E1[12], EBr[12];
    float rs0h = 0.f, rs1h = 0.f, rsBh = 0.f;
    #pragma unroll
    for (int k = 0; k < 12; ++k) {
        int j0 = jb + 2 * k, j1 = jb + 2 * k + 1;
        float a0 = __expf(fwd ? trans[r0 * KTAGS + j0] : trans[j0 * KTAGS + r0]);
        float a1 = __expf(fwd ? trans[r0 * KTAGS + j1] : trans[j1 * KTAGS + r0]);
        rs0h += a0 + a1;
        E0[k] = pk2(a0, a1);
        float b0 = __expf(fwd ? trans[r1 * KTAGS + j0] : trans[j0 * KTAGS + r1]);
        float b1 = __expf(fwd ? trans[r1 * KTAGS + j1] : trans[j1 * KTAGS + r1]);
        rs1h += b0 + b1;
        E1[k] = pk2(b0, b1);
        float c0 = __expf(fwd ? trans[rB * KTAGS + j0] : trans[j0 * KTAGS + rB]);
        float c1 = __expf(fwd ? trans[rB * KTAGS + j1] : trans[j1 * KTAGS + rB]);
        rsBh += c0 + c1;
        EBr[k] = pk2(c0, c1);
    }
    const float rs0 = rs0h + __shfl_xor_sync(0xffffffffu, rs0h, 16);
    const float rs1 = rs1h + __shfl_xor_sync(0xffffffffu, rs1h, 16);
    const float rsB = rsBh + __shfl_xor_sync(0xffffffffu, rsBh, 16);

    const float* ebX = h_tag + (size_t)bX * TLEN * KTAGS;
    const float* mbX = mask + (size_t)bX * TLEN;
    const float* ebY = h_tag + (size_t)bY * TLEN * KTAGS;
    const float* mbY = mask + (size_t)bY * TLEN;

    float x0, x1, xB, y0, y1, yB;
    double M0X = 0.0, M0Y = 0.0;
    int MintX = 0, MintY = 0;

    if (fwd) {
        // ---- special step t = 0 per chain (log domain, exact) ----
        const float lg0 = __logf(1.0f + rs0);
        const float lg1 = __logf(1.0f + rs1);
        const float lgB = __logf(1.0f + rsB);
        {
            float m0 = mbX[0];
            float s0 = NEGV + lg0 + ebX[r0];
            float s1 = NEGV + lg1 + ebX[r1];
            float sB = NEGV + lgB + ebX[rB];
            s0 = (m0 != 0.f) ? s0 : NEGV;
            s1 = (m0 != 0.f) ? s1 : NEGV;
            sB = (m0 != 0.f) ? sB : ((rB == STOPID) ? 0.f : NEGV);
            float loc = fmaxf(fmaxf(s0, s1), sB);
            #pragma unroll
            for (int o = 16; o; o >>= 1)
                loc = fmaxf(loc, __shfl_xor_sync(0xffffffffu, loc, o));
            M0X = (double)loc;
            x0 = __expf(s0 - loc); x1 = __expf(s1 - loc); xB = __expf(sB - loc);
        }
        {
            float m0 = mbY[0];
            float s0 = NEGV + lg0 + ebY[r0];
            float s1 = NEGV + lg1 + ebY[r1];
            float sB = NEGV + lgB + ebY[rB];
            s0 = (m0 != 0.f) ? s0 : NEGV;
            s1 = (m0 != 0.f) ? s1 : NEGV;
            sB = (m0 != 0.f) ? sB : ((rB == STOPID) ? 0.f : NEGV);
            float loc = fmaxf(fmaxf(s0, s1), sB);
            #pragma unroll
            for (int o = 16; o; o >>= 1)
                loc = fmaxf(loc, __shfl_xor_sync(0xffffffffu, loc, o));
            M0Y = (double)loc;
            y0 = __expf(s0 - loc); y1 = __expf(s1 - loc); yB = __expf(sB - loc);
        }
    } else {
        // beta_{1023}(i) = exp(trans[STOP, i]); identical init for both chains
        x0 = __expf(trans[STOPID * KTAGS + r0]);
        x1 = __expf(trans[STOPID * KTAGS + r1]);
        xB = __expf(trans[STOPID * KTAGS + rB]);
        y0 = x0; y1 = x1; yB = xB;
    }

    if (fwd)
        run_chain2<true >(ebX, mbX, ebY, mbY, E0, E1, EBr,
                          x0, x1, xB, MintX, y0, y1, yB, MintY,
                          &vbuf[warp][0][0][0], &vbuf[warp][0][1][0],
                          &vbuf[warp][1][0][0], &vbuf[warp][1][1][0], lane);
    else
        run_chain2<false>(ebX, mbX, ebY, mbY, E0, E1, EBr,
                          x0, x1, xB, MintX, y0, y1, yB, MintY,
                          &vbuf[warp][0][0][0], &vbuf[warp][0][1][0],
                          &vbuf[warp][1][0][0], &vbuf[warp][1][1][0], lane);

    // ---- publish results: cbuf[dir][localBatch][tag] ----
    const int di = fwd ? 0 : 1;
    if (lo) {
        cbuf[di][bloc][r0] = x0;     cbuf[di][bloc][r1] = x1;
        cbuf[di][bloc + 1][r0] = y0; cbuf[di][bloc + 1][r1] = y1;
    } else {
        cbuf[di][bloc][rB] = xB;
        cbuf[di][bloc + 1][rB] = yB;
    }
    if (lane == 0) {
        Msh[di][bloc]     = M0X + (double)MintX * 0.6931471805599453;
        Msh[di][bloc + 1] = M0Y + (double)MintY * 0.6931471805599453;
    }
    __syncthreads();

    // ---- combine: Z = Mf + Mb + log(sum_i alpha_i * beta_i) ----
    if (fwd) {
        #pragma unroll
        for (int c = 0; c < 2; ++c) {
            int bl = bloc + c;
            float fin = cbuf[0][bl][lane] * cbuf[1][bl][lane];
            if (lo) fin += cbuf[0][bl][32 + lane] * cbuf[1][bl][32 + lane];
            #pragma unroll
            for (int o = 16; o; o >>= 1)
                fin += __shfl_xor_sync(0xffffffffu, fin, o);
            int bg = blockIdx.x * 4 + bl;
            if (lane == 0 && bg < B)
                out[bg] = (float)(Msh[0][bl] + Msh[1][bl] + (double)__logf(fin));
        }
    }
}

extern "C" void kernel_launch(void* const* d_in, const int* in_sizes, int n_in,
                              void* d_out, int out_size) {
    const float* h_tag = (const float*)d_in[0];
    const float* msk   = (const float*)d_in[1];
    const float* trans = (const float*)d_in[2];
    float* out = (float*)d_out;
    int B = in_sizes[0] / (TLEN * KTAGS);
    int blocks = (B + 3) / 4;
    CRF_29265907155259_kernel<<<blocks, 128>>>(h_tag, msk, trans, out, B);
}